// round 9
// baseline (speedup 1.0000x reference)
#include <cuda_runtime.h>
#include <math.h>

// x:[32,512,56,56] f32, w1:[32,512], w2:[512,32]
// out = concat(scaled [32,512,56,56], comp [32,512])

#define B 32
#define C 512
#define CR 32
#define HW 3136
#define HW4 784
#define BC (B*C)            // 16384
#define HBC (BC/2)          // 8192
#define NTOT (B*C*HW)
#define N4 (NTOT/4)         // 12845056 float4s
#define HALF4 (N4/2)        // 6422528 (= 8192*784)

#define NBLOCKS 592                 // 148x4; all co-resident (GB300 has 152 SMs)
#define NTHREADS (NBLOCKS*256)
#define NWARPS (NBLOCKS*8)          // 4736

__device__ float g_y[BC];
__device__ float g_gate[BC];
__device__ unsigned g_cnt[B];     // monotonic: +512 per batch per launch
__device__ unsigned g_ready[B];   // last epoch whose gates are published
__device__ unsigned g_blk_cnt;    // monotonic block-arrival counter -> epoch

__device__ __forceinline__ unsigned ld_acquire(const unsigned* p) {
    unsigned v;
    asm volatile("ld.global.acquire.gpu.u32 %0, [%1];" : "=r"(v) : "l"(p));
    return v;
}
__device__ __forceinline__ void st_release(unsigned* p, unsigned v) {
    asm volatile("st.global.release.gpu.u32 [%0], %1;" :: "l"(p), "r"(v));
}

// Warp-level MLP for one batch b: h = relu(y@w1^T) (32), gates+comp for 512 c.
// Runs in the warp whose atomicAdd completed the batch. h kept in smem slot.
__device__ __forceinline__ void warp_mlp(int b, int warp, int lane,
                                         const float* __restrict__ w1,
                                         const float* __restrict__ w2,
                                         float* __restrict__ comp,
                                         float (*h_s)[CR],
                                         unsigned epoch) {
    // y[b, k*32+lane] into registers (coalesced)
    float yreg[16];
    #pragma unroll
    for (int k = 0; k < 16; k++)
        yreg[k] = g_y[b * C + k * 32 + lane];

    // h[r] = relu(sum_c y[c]*w1[r][c]); butterfly leaves full sum in all lanes
    #pragma unroll 4
    for (int r = 0; r < CR; r++) {
        const float* __restrict__ w1r = w1 + r * C;
        float acc = 0.f;
        #pragma unroll
        for (int k = 0; k < 16; k++)
            acc += yreg[k] * w1r[k * 32 + lane];
        #pragma unroll
        for (int o = 16; o > 0; o >>= 1)
            acc += __shfl_xor_sync(0xFFFFFFFFu, acc, o);
        if (lane == 0) h_s[warp][r] = fmaxf(acc, 0.f);
    }
    __syncwarp();

    // gates + comp: lane handles c = k*32+lane (y for it is yreg[k])
    #pragma unroll 2
    for (int k = 0; k < 16; k++) {
        const int c = k * 32 + lane;
        const float4* __restrict__ w2c = reinterpret_cast<const float4*>(w2 + c * CR);
        float acc = 0.f;
        #pragma unroll
        for (int j = 0; j < 8; j++) {
            float4 w = w2c[j];
            acc += h_s[warp][4*j+0]*w.x + h_s[warp][4*j+1]*w.y
                 + h_s[warp][4*j+2]*w.z + h_s[warp][4*j+3]*w.w;
        }
        const float g = 1.0f / (1.0f + expf(-acc));
        const int idx = b * C + c;
        g_gate[idx] = g;
        comp[idx] = yreg[k] * (1.0f - g);
    }
    __syncwarp();
    __threadfence();
    if (lane == 0) st_release(&g_ready[b], epoch);
}

// Reduce one channel pair (c0, c0+8192) with interleaved streams; publish
// counts; run the MLP for any batch this warp completes.
__device__ __forceinline__ void reduce_pair(int c0, int warp, int lane,
                                            const float4* __restrict__ xp4,
                                            const float* __restrict__ w1,
                                            const float* __restrict__ w2,
                                            float* __restrict__ comp,
                                            float (*h_s)[CR],
                                            unsigned epoch) {
    const float4* __restrict__ xp0 = xp4 + (size_t)c0 * HW4;
    const float4* __restrict__ xp1 = xp0 + (size_t)HBC * HW4;

    float s0 = 0.f, s1 = 0.f;
    int j = lane;
    #pragma unroll 6
    for (int k = 0; k < 24; k++, j += 32) {
        float4 a = __ldcs(&xp0[j]);
        float4 b = __ldcs(&xp1[j]);
        s0 += (a.x + a.y) + (a.z + a.w);
        s1 += (b.x + b.y) + (b.z + b.w);
    }
    if (lane < 16) {                       // 784 = 24*32 + 16
        float4 a = __ldcs(&xp0[768 + lane]);
        float4 b = __ldcs(&xp1[768 + lane]);
        s0 += (a.x + a.y) + (a.z + a.w);
        s1 += (b.x + b.y) + (b.z + b.w);
    }
    #pragma unroll
    for (int o = 16; o > 0; o >>= 1) {
        s0 += __shfl_xor_sync(0xFFFFFFFFu, s0, o);
        s1 += __shfl_xor_sync(0xFFFFFFFFu, s1, o);
    }

    const int b0 = c0 >> 9;            // batch of c0
    const int b1 = b0 + 16;            // batch of c0+8192
    unsigned trig = 0;
    if (lane == 0) {
        g_y[c0]       = s0 * (1.0f / HW);
        g_y[c0 + HBC] = s1 * (1.0f / HW);
        __threadfence();               // publish y before counting
        unsigned o0 = atomicAdd(&g_cnt[b0], 1u);
        unsigned o1 = atomicAdd(&g_cnt[b1], 1u);
        trig = ((o0 & 511u) == 511u ? 1u : 0u) | ((o1 & 511u) == 511u ? 2u : 0u);
    }
    trig = __shfl_sync(0xFFFFFFFFu, trig, 0);
    if (trig & 1u) { __threadfence(); warp_mlp(b0, warp, lane, w1, w2, comp, h_s, epoch); }
    if (trig & 2u) { __threadfence(); warp_mlp(b1, warp, lane, w1, w2, comp, h_s, epoch); }
}

__global__ void __launch_bounds__(256, 4)
se_fused(const float* __restrict__ x,
         const float* __restrict__ w1,
         const float* __restrict__ w2,
         float* __restrict__ out) {
    __shared__ float h_s[8][CR];
    __shared__ unsigned epoch_s;

    const int tid  = threadIdx.x;
    const int warp = tid >> 5;
    const int lane = tid & 31;
    const float4* __restrict__ xp4 = reinterpret_cast<const float4*>(x);
    float* __restrict__ comp = out + NTOT;

    if (tid == 0)
        epoch_s = atomicAdd(&g_blk_cnt, 1u) / NBLOCKS + 1u;
    __syncthreads();
    const unsigned epoch = epoch_s;

    // ---- Reduce phase: warp W handles pair(W) and, if W<3456, pair(W+4736).
    const int W = blockIdx.x * 8 + warp;
    reduce_pair(W, warp, lane, xp4, w1, w2, comp, h_s, epoch);
    if (W < 3456)
        reduce_pair(W + 4736, warp, lane, xp4, w1, w2, comp, h_s, epoch);

    // ---- Apply phase: two distant coalesced streams, spin on batch flags.
    float4* __restrict__ op = reinterpret_cast<float4*>(out);
    int last_b0 = -1;
    for (int t = blockIdx.x * 256 + tid; t < HALF4; t += NTHREADS) {
        const int bc0 = t / HW4;
        const int b0 = bc0 >> 9;
        if (b0 != last_b0) {
            while (ld_acquire(&g_ready[b0])      < epoch) {}
            while (ld_acquire(&g_ready[b0 + 16]) < epoch) {}
            last_b0 = b0;
        }
        const int i1 = t + HALF4;
        const float g0 = __ldcg(&g_gate[bc0]);
        const float g1 = __ldcg(&g_gate[bc0 + HBC]);
        float4 v0 = __ldcs(&xp4[t]);
        float4 v1 = __ldcs(&xp4[i1]);
        v0.x *= g0; v0.y *= g0; v0.z *= g0; v0.w *= g0;
        v1.x *= g1; v1.y *= g1; v1.z *= g1; v1.w *= g1;
        __stcs(&op[t],  v0);
        __stcs(&op[i1], v1);
    }
}

// ---------------------------------------------------------------------------
extern "C" void kernel_launch(void* const* d_in, const int* in_sizes, int n_in,
                              void* d_out, int out_size) {
    const float* x  = (const float*)d_in[0];
    const float* w1 = (const float*)d_in[1];
    const float* w2 = (const float*)d_in[2];
    float* out = (float*)d_out;

    se_fused<<<NBLOCKS, 256>>>(x, w1, w2, out);
}

// round 10
// speedup vs baseline: 1.6804x; 1.6804x over previous
#include <cuda_runtime.h>
#include <math.h>

// x:[32,512,56,56] f32, w1:[32,512], w2:[512,32]
// out = concat(scaled [32,512,56,56], comp [32,512])

#define B 32
#define C 512
#define CR 32
#define HW 3136
#define HW4 784
#define BC (B*C)            // 16384
#define HBC (BC/2)          // 8192
#define NTOT (B*C*HW)
#define N4 (NTOT/4)         // 12845056 float4s
#define HALF4 (N4/2)        // 6422528 (= 8192*784, channel-aligned)
#define APPLY_BLOCKS (HALF4/256)   // 25088 exactly
#define REDUCE_BLOCKS (BC/8)       // 2048: one warp per bc

__device__ float g_y[BC];
__device__ float g_gate[BC];
__device__ unsigned g_cnt[B];   // monotonic per-batch arrival counter (+512/launch)

// ---------------------------------------------------------------------------
// Warp-level MLP for one batch b (runs in the warp that completed the batch):
// h = relu(y@w1^T) [32]; gate = sigmoid(h@w2^T) [512]; comp = y*(1-gate).
// Verified correct in R9 (same rel_err as split version).
// ---------------------------------------------------------------------------
__device__ __forceinline__ void warp_mlp(int b, int warp, int lane,
                                         const float* __restrict__ w1,
                                         const float* __restrict__ w2,
                                         float* __restrict__ comp,
                                         float (*h_s)[CR]) {
    // y[b, k*32+lane] into registers (coalesced)
    float yreg[16];
    #pragma unroll
    for (int k = 0; k < 16; k++)
        yreg[k] = g_y[b * C + k * 32 + lane];

    // h[r] = relu(sum_c y[c]*w1[r][c])
    #pragma unroll 4
    for (int r = 0; r < CR; r++) {
        const float* __restrict__ w1r = w1 + r * C;
        float acc = 0.f;
        #pragma unroll
        for (int k = 0; k < 16; k++)
            acc += yreg[k] * w1r[k * 32 + lane];
        #pragma unroll
        for (int o = 16; o > 0; o >>= 1)
            acc += __shfl_xor_sync(0xFFFFFFFFu, acc, o);
        if (lane == 0) h_s[warp][r] = fmaxf(acc, 0.f);
    }
    __syncwarp();

    // gates + comp: lane handles c = k*32+lane
    #pragma unroll 2
    for (int k = 0; k < 16; k++) {
        const int c = k * 32 + lane;
        const float4* __restrict__ w2c = reinterpret_cast<const float4*>(w2 + c * CR);
        float acc = 0.f;
        #pragma unroll
        for (int j = 0; j < 8; j++) {
            float4 w = w2c[j];
            acc += h_s[warp][4*j+0]*w.x + h_s[warp][4*j+1]*w.y
                 + h_s[warp][4*j+2]*w.z + h_s[warp][4*j+3]*w.w;
        }
        const float g = 1.0f / (1.0f + expf(-acc));
        const int idx = b * C + c;
        g_gate[idx] = g;
        comp[idx] = yreg[k] * (1.0f - g);
    }
}

// ---------------------------------------------------------------------------
// Kernel 1: reduce (R6 pattern: one warp per bc, 8 warps/block, __ldcs) +
// counter-triggered per-batch MLP in the completing warp.
// ---------------------------------------------------------------------------
__global__ __launch_bounds__(256) void k_reduce_mlp(const float* __restrict__ x,
                                                    const float* __restrict__ w1,
                                                    const float* __restrict__ w2,
                                                    float* __restrict__ comp) {
    __shared__ float h_s[8][CR];
    const int warp = threadIdx.x >> 5;
    const int lane = threadIdx.x & 31;
    const int bc = blockIdx.x * 8 + warp;
    const float4* __restrict__ xp = reinterpret_cast<const float4*>(x) + (size_t)bc * HW4;

    float s = 0.f;
    int j = lane;
    #pragma unroll 6
    for (int k = 0; k < 24; k++, j += 32) {
        float4 v = __ldcs(&xp[j]);
        s += (v.x + v.y) + (v.z + v.w);
    }
    if (lane < 16) {                       // 784 = 24*32 + 16
        float4 v = __ldcs(&xp[768 + lane]);
        s += (v.x + v.y) + (v.z + v.w);
    }
    #pragma unroll
    for (int o = 16; o > 0; o >>= 1)
        s += __shfl_xor_sync(0xFFFFFFFFu, s, o);

    const int b = bc >> 9;                 // batch index
    unsigned trig = 0;
    if (lane == 0) {
        g_y[bc] = s * (1.0f / HW);
        __threadfence();                   // publish y before counting
        unsigned old = atomicAdd(&g_cnt[b], 1u);
        trig = ((old & 511u) == 511u) ? 1u : 0u;   // monotonic: replay-safe
    }
    trig = __shfl_sync(0xFFFFFFFFu, trig, 0);
    if (trig) {
        __threadfence();                   // ensure all producers' y visible
        warp_mlp(b, warp, lane, w1, w2, comp, h_s);
    }
}

// ---------------------------------------------------------------------------
// Kernel 2: scaled = x * gate[bc]. TWO fully-coalesced distant streams per
// thread (i, i+HALF4). Measured ~7 TB/s (LTS cap). Exact grid, streaming.
// ---------------------------------------------------------------------------
__global__ __launch_bounds__(256) void k_apply_gate(const float* __restrict__ x,
                                                    float* __restrict__ out) {
    const int i0 = blockIdx.x * 256 + threadIdx.x;
    const int i1 = i0 + HALF4;

    const float4* __restrict__ xp = reinterpret_cast<const float4*>(x);
    float4* __restrict__ op = reinterpret_cast<float4*>(out);

    const float g0 = __ldg(&g_gate[i0 / HW4]);
    const float g1 = __ldg(&g_gate[i1 / HW4]);

    float4 v0 = __ldcs(&xp[i0]);
    float4 v1 = __ldcs(&xp[i1]);
    v0.x *= g0; v0.y *= g0; v0.z *= g0; v0.w *= g0;
    v1.x *= g1; v1.y *= g1; v1.z *= g1; v1.w *= g1;
    __stcs(&op[i0], v0);
    __stcs(&op[i1], v1);
}

// ---------------------------------------------------------------------------
extern "C" void kernel_launch(void* const* d_in, const int* in_sizes, int n_in,
                              void* d_out, int out_size) {
    const float* x  = (const float*)d_in[0];
    const float* w1 = (const float*)d_in[1];
    const float* w2 = (const float*)d_in[2];
    float* out = (float*)d_out;

    float* scaled = out;
    float* comp   = out + NTOT;

    k_reduce_mlp<<<REDUCE_BLOCKS, 256>>>(x, w1, w2, comp);
    k_apply_gate<<<APPLY_BLOCKS, 256>>>(x, scaled);
}

// round 11
// speedup vs baseline: 1.9524x; 1.1619x over previous
#include <cuda_runtime.h>
#include <math.h>

// x:[32,512,56,56] f32, w1:[32,512], w2:[512,32]
// out = concat(scaled [32,512,56,56], comp [32,512])
//
// Final structure (measured best, R6 = 100.5 us):
//   k_reduce_mean : 34.6 us @ ~6.0 TB/s (pure-read ceiling)
//   k_mlp         : ~2.5 us (tiny)
//   k_apply_gate  : ~59 us @ ~7.0 TB/s (r+w mix ceiling)
// comp = y*(1-gate) algebraic identity avoids a third pass over x.

#define B 32
#define C 512
#define CR 32
#define HW 3136
#define HW4 784
#define BC (B*C)            // 16384
#define NTOT (B*C*HW)
#define N4 (NTOT/4)         // 12845056 float4s
#define HALF4 (N4/2)        // 6422528 (= 8192*784, channel-aligned)
#define APPLY_BLOCKS (HALF4/256)   // 25088 exactly

__device__ float g_y[BC];
__device__ float g_gate[BC];

// ---------------------------------------------------------------------------
// Kernel 1: y[bc] = mean(x[bc,:]). One WARP per bc, 8 warps/block.
// Lane-strided float4 loads, __ldcs (zero reuse). regs=29 -> high occupancy.
// ---------------------------------------------------------------------------
__global__ __launch_bounds__(256) void k_reduce_mean(const float* __restrict__ x) {
    const int warp = threadIdx.x >> 5;
    const int lane = threadIdx.x & 31;
    const int bc = blockIdx.x * 8 + warp;
    const float4* __restrict__ xp = reinterpret_cast<const float4*>(x) + (size_t)bc * HW4;

    float s = 0.f;
    int j = lane;
    #pragma unroll 6
    for (int k = 0; k < 24; k++, j += 32) {
        float4 v = __ldcs(&xp[j]);
        s += (v.x + v.y) + (v.z + v.w);
    }
    if (lane < 16) {                       // 784 = 24*32 + 16
        float4 v = __ldcs(&xp[768 + lane]);
        s += (v.x + v.y) + (v.z + v.w);
    }
    #pragma unroll
    for (int o = 16; o > 0; o >>= 1)
        s += __shfl_xor_sync(0xFFFFFFFFu, s, o);
    if (lane == 0) g_y[bc] = s * (1.0f / HW);
}

// ---------------------------------------------------------------------------
// Kernel 2 (fused MLP): one block per b, 512 threads.
// Phase 1: h[r]=relu(sum_c y[b][c]*w1[r][c]); 16 warps, 2 r's per warp.
// Phase 2: g[b][c]=sigmoid(sum_r h[r]*w2[c][r]); one thread per c.
//          comp[b][c]=y[b][c]*(1-g)  (gate constant over H,W).
// ---------------------------------------------------------------------------
__global__ __launch_bounds__(512) void k_mlp(const float* __restrict__ w1,
                                             const float* __restrict__ w2,
                                             float* __restrict__ comp_out) {
    __shared__ float y_s[C];
    __shared__ float h_s[CR];
    const int b = blockIdx.x;
    const int tid = threadIdx.x;

    y_s[tid] = g_y[b * C + tid];
    __syncthreads();

    const int warp = tid >> 5;
    const int lane = tid & 31;
    #pragma unroll
    for (int r2 = 0; r2 < 2; r2++) {
        const int r = warp * 2 + r2;
        const float* __restrict__ w1r = w1 + r * C;
        float acc = 0.f;
        #pragma unroll
        for (int c = lane; c < C; c += 32)
            acc += y_s[c] * w1r[c];
        #pragma unroll
        for (int o = 16; o > 0; o >>= 1)
            acc += __shfl_xor_sync(0xFFFFFFFFu, acc, o);
        if (lane == 0) h_s[r] = fmaxf(acc, 0.f);
    }
    __syncthreads();

    const int c = tid;
    const float4* __restrict__ w2c = reinterpret_cast<const float4*>(w2 + c * CR);
    float acc = 0.f;
    #pragma unroll
    for (int j = 0; j < 8; j++) {
        float4 w = w2c[j];
        acc += h_s[4*j+0] * w.x + h_s[4*j+1] * w.y + h_s[4*j+2] * w.z + h_s[4*j+3] * w.w;
    }
    const float g = 1.0f / (1.0f + expf(-acc));
    const int idx = b * C + c;
    g_gate[idx] = g;
    comp_out[idx] = y_s[c] * (1.0f - g);
}

// ---------------------------------------------------------------------------
// Kernel 3: scaled = x * gate[bc]. TWO fully-coalesced distant streams per
// thread (i and i+HALF4): consecutive lanes -> consecutive float4s in both
// streams (4 lines per warp-load, minimum). HALF4 multiple of HW4 keeps both
// halves channel-aligned. Exact grid, streaming hints. Measured ~7 TB/s.
// ---------------------------------------------------------------------------
__global__ __launch_bounds__(256) void k_apply_gate(const float* __restrict__ x,
                                                    float* __restrict__ out) {
    const int i0 = blockIdx.x * 256 + threadIdx.x;
    const int i1 = i0 + HALF4;

    const float4* __restrict__ xp = reinterpret_cast<const float4*>(x);
    float4* __restrict__ op = reinterpret_cast<float4*>(out);

    const float g0 = __ldg(&g_gate[i0 / HW4]);
    const float g1 = __ldg(&g_gate[i1 / HW4]);

    float4 v0 = __ldcs(&xp[i0]);
    float4 v1 = __ldcs(&xp[i1]);
    v0.x *= g0; v0.y *= g0; v0.z *= g0; v0.w *= g0;
    v1.x *= g1; v1.y *= g1; v1.z *= g1; v1.w *= g1;
    __stcs(&op[i0], v0);
    __stcs(&op[i1], v1);
}

// ---------------------------------------------------------------------------
extern "C" void kernel_launch(void* const* d_in, const int* in_sizes, int n_in,
                              void* d_out, int out_size) {
    const float* x  = (const float*)d_in[0];
    const float* w1 = (const float*)d_in[1];
    const float* w2 = (const float*)d_in[2];
    float* out = (float*)d_out;

    float* scaled = out;
    float* comp   = out + NTOT;

    k_reduce_mean<<<BC / 8, 256>>>(x);
    k_mlp<<<B, 512>>>(w1, w2, comp);
    k_apply_gate<<<APPLY_BLOCKS, 256>>>(x, scaled);
}